// round 12
// baseline (speedup 1.0000x reference)
#include <cuda_runtime.h>
#include <cuda_fp16.h>
#include <math_constants.h>
#include <cstdint>

// Round 12: block-heterogeneous self-masking fusion.
//  - R8 attention kernel (BM=64, 128 thr, 2 blocks/SM) + each block computes
//    its OWN threefry keep-words in-kernel; separate mask kernel deleted.
//  - Anti-phase-lock: slot-mates on an SM are bids b and b+148, so blocks with
//    even (bid/148) compute the mask UPFRONT (smem), odd blocks compute it
//    LAZILY one k-tile ahead (registers). One block front-loads ALU while its
//    SM-mate runs the tensor-heavy body -> mask ALU hides under attn tensor.
//  - No cross-block communication: no races, no flags, no deadlock.
// Mask bits + arithmetic bit-identical -> rel_err 1.5387e-4.

#define S_LEN 2048
#define D_DIM 128
#define BM 64
#define BN 64
#define NT 128
#define NELEM (2 * 16 * S_LEN * D_DIM)

#define TILE_B 17408                    // one 64x128 fp16 tile (64*272)
#define KBUF_B (2 * TILE_B)
#define OFF_K0 0
#define OFF_K1 KBUF_B                   // 34816
#define OFF_V  (2 * KBUF_B)             // 69632
#define OFF_MK (OFF_V + TILE_B)         // 87040: mask words 32 kt x 128 tid
#define SMEM_BYTES (OFF_MK + 32 * 128 * 4)   // 103424 ; x2 blocks = 206848 <= 227KB

__device__ __half g_Kh[NELEM];
__device__ __half g_Kl[NELEM];
__device__ __half g_Vh[NELEM];

// ---------------- prologue: fp32 -> fp16 hi/lo conversion ----------------
__global__ void __launch_bounds__(256, 4)
convert_kernel(const float* __restrict__ x1, const float* __restrict__ x2)
{
    int stride = gridDim.x * blockDim.x;
    for (int i = blockIdx.x * blockDim.x + threadIdx.x; i < NELEM / 4; i += stride) {
        float4 k = reinterpret_cast<const float4*>(x2)[i];
        float4 v = reinterpret_cast<const float4*>(x1)[i];
        __half h0 = __float2half_rn(k.x), h1 = __float2half_rn(k.y);
        __half h2 = __float2half_rn(k.z), h3 = __float2half_rn(k.w);
        __half e0 = __float2half_rn(k.x - __half2float(h0));
        __half e1 = __float2half_rn(k.y - __half2float(h1));
        __half e2 = __float2half_rn(k.z - __half2float(h2));
        __half e3 = __float2half_rn(k.w - __half2float(h3));
        reinterpret_cast<__half2*>(g_Kh)[2*i]   = __halves2half2(h0, h1);
        reinterpret_cast<__half2*>(g_Kh)[2*i+1] = __halves2half2(h2, h3);
        reinterpret_cast<__half2*>(g_Kl)[2*i]   = __halves2half2(e0, e1);
        reinterpret_cast<__half2*>(g_Kl)[2*i+1] = __halves2half2(e2, e3);
        reinterpret_cast<__half2*>(g_Vh)[2*i] =
            __halves2half2(__float2half_rn(v.x), __float2half_rn(v.y));
        reinterpret_cast<__half2*>(g_Vh)[2*i+1] =
            __halves2half2(__float2half_rn(v.z), __float2half_rn(v.w));
    }
}

// ---------------- threefry (JAX partitionable, key=(0,42)), trimmed ----------------
// Returns y with MSB==1 iff KEEP (u < 0.5). Bit-exact (validated R11).
__device__ __forceinline__ unsigned tf_rotl(unsigned x, int r) {
    return __funnelshift_l(x, x, r);
}
__device__ __forceinline__ unsigned threefry_keep_msb(unsigned g) {
    const unsigned ks1 = 42u;
    const unsigned ks2 = 0x1BD11BDAu ^ 42u;
    unsigned x0 = 0u;
    unsigned x1 = g + ks1;
#define TF_R(r)            { x0 += x1; x1 = tf_rotl(x1, (r)) ^ x0; }
#define TF_IR(ka, kb, r)   { x1 += (kb); x0 = x0 + (ka) + x1; x1 = tf_rotl(x1, (r)) ^ x0; }
    TF_R(13) TF_R(15) TF_R(26) TF_R(6)
    TF_IR(ks1, ks2 + 1u, 17) TF_R(29) TF_R(16) TF_R(24)
    TF_IR(ks2, 2u,       13) TF_R(15) TF_R(26) TF_R(6)
    TF_IR(0u,  ks1 + 3u, 17) TF_R(29) TF_R(16) TF_R(24)
    TF_IR(ks1, ks2 + 4u, 13) TF_R(15) TF_R(26) TF_R(6)
#undef TF_R
#undef TF_IR
    return ~((x0 + ks2) ^ (x1 + 5u));   // XNOR: single LOP3
}

// keep-word for one k-tile: 32 bits, bit t (t=4n+j) at position t.
__device__ __forceinline__ uint32_t tile_mask_word(unsigned gt)
{
    uint32_t keepbits = 0u;
    #pragma unroll
    for (int n = 0; n < 8; ++n) {
        unsigned gi = gt + (unsigned)(8 * n);
        unsigned y0 = threefry_keep_msb(gi);
        unsigned y1 = threefry_keep_msb(gi + 1u);
        unsigned y2 = threefry_keep_msb(gi + 16384u);
        unsigned y3 = threefry_keep_msb(gi + 16385u);
        keepbits = (keepbits >> 1) | (y0 & 0x80000000u);
        keepbits = (keepbits >> 1) | (y1 & 0x80000000u);
        keepbits = (keepbits >> 1) | (y2 & 0x80000000u);
        keepbits = (keepbits >> 1) | (y3 & 0x80000000u);
    }
    return keepbits;
}

__device__ __forceinline__ uint32_t packh2(__half a, __half b) {
    __half2 h = __halves2half2(a, b);
    return *reinterpret_cast<uint32_t*>(&h);
}
__device__ __forceinline__ void mma_f16(float c[4], const uint32_t a[4],
                                        uint32_t b0, uint32_t b1) {
    asm volatile(
        "mma.sync.aligned.m16n8k16.row.col.f32.f16.f16.f32 "
        "{%0,%1,%2,%3}, {%4,%5,%6,%7}, {%8,%9}, {%0,%1,%2,%3};\n"
        : "+f"(c[0]), "+f"(c[1]), "+f"(c[2]), "+f"(c[3])
        : "r"(a[0]), "r"(a[1]), "r"(a[2]), "r"(a[3]), "r"(b0), "r"(b1));
}
__device__ __forceinline__ void ldsm_x4(uint32_t& r0, uint32_t& r1,
                                        uint32_t& r2, uint32_t& r3, uint32_t addr) {
    asm volatile("ldmatrix.sync.aligned.m8n8.x4.shared.b16 {%0,%1,%2,%3}, [%4];"
                 : "=r"(r0), "=r"(r1), "=r"(r2), "=r"(r3) : "r"(addr));
}
__device__ __forceinline__ void ldsm_x4_t(uint32_t& r0, uint32_t& r1,
                                          uint32_t& r2, uint32_t& r3, uint32_t addr) {
    asm volatile("ldmatrix.sync.aligned.m8n8.x4.trans.shared.b16 {%0,%1,%2,%3}, [%4];"
                 : "=r"(r0), "=r"(r1), "=r"(r2), "=r"(r3) : "r"(addr));
}
__device__ __forceinline__ void cp_async16(uint32_t dst, const void* src) {
    asm volatile("cp.async.cg.shared.global [%0], [%1], 16;" :: "r"(dst), "l"(src));
}
__device__ __forceinline__ void cp_commit() { asm volatile("cp.async.commit_group;"); }
template <int N> __device__ __forceinline__ void cp_wait() {
    asm volatile("cp.async.wait_group %0;" :: "n"(N));
}

__device__ __forceinline__ void stage_k(uint32_t buf_b, int bh, int k0, int tid)
{
    const size_t kbase = (size_t)bh * (S_LEN * D_DIM) + (size_t)k0 * D_DIM;
    #pragma unroll
    for (int it = 0; it < 16; ++it) {
        int id  = tid + it * NT;
        int arr = id >> 10;
        int rem = id & 1023;
        int row = rem >> 4;
        int col = rem & 15;
        uint32_t dst = buf_b + (uint32_t)(arr * TILE_B + row * 272 + col * 16);
        const __half* src = (arr ? g_Kl : g_Kh) + kbase + (size_t)row * D_DIM + col * 8;
        cp_async16(dst, src);
    }
}
__device__ __forceinline__ void stage_v(uint32_t vbuf_b, int bh, int k0, int tid)
{
    const size_t kbase = (size_t)bh * (S_LEN * D_DIM) + (size_t)k0 * D_DIM;
    #pragma unroll
    for (int it = 0; it < 8; ++it) {
        int id  = tid + it * NT;
        int row = id >> 4;
        int col = id & 15;
        cp_async16(vbuf_b + (uint32_t)(row * 272 + col * 16),
                   g_Vh + kbase + (size_t)row * D_DIM + col * 8);
    }
}

__global__ void __launch_bounds__(NT, 2)
attn_mma_kernel(const float* __restrict__ x1,
                const float* __restrict__ x2,
                const float* __restrict__ x3,
                float* __restrict__ out)
{
    extern __shared__ __half smh[];
    uint32_t* smask = reinterpret_cast<uint32_t*>(
        reinterpret_cast<char*>(smh) + OFF_MK);

    const int tid  = threadIdx.x;
    const int warp = tid >> 5;
    const int lane = tid & 31;
    const int g    = lane >> 2;
    const int c    = lane & 3;
    const int bh   = blockIdx.y;
    const int q0   = blockIdx.x * BM;
    const int qrow = q0 + warp * 16 + g;

    // SM slot-mates are bids b and b+148 -> (bid/148) parity differs.
    const int bid = blockIdx.y * 32 + blockIdx.x;
    const bool upfront = ((bid / 148) & 1) == 0;

    const float* Q = x1 + (size_t)bh * (S_LEN * D_DIM);
    const float* R = x2 + (size_t)bh * (S_LEN * D_DIM);
    float* O = out + (size_t)bh * (S_LEN * D_DIM);
    const float scl = (1.0f / x3[bh]) * 1.4426950408889634f;

    // dropout index base for this thread's fragment rows
    const unsigned gbase = ((unsigned)bh * 2048u + (unsigned)qrow) * 2048u
                         + (unsigned)(2 * c);

    const uint32_t smem_u32 = (uint32_t)__cvta_generic_to_shared(smh);

    stage_k(smem_u32 + OFF_K0, bh, 0, tid);
    cp_commit();

    // ---- Q fragments resident (hi + lo split) ----
    uint32_t qh[8][4], ql[8][4];
    #pragma unroll
    for (int t = 0; t < 8; ++t) {
        #pragma unroll
        for (int p = 0; p < 4; ++p) {
            int row = qrow + (p & 1) * 8;
            int col = 16 * t + (p >> 1) * 8 + 2 * c;
            float2 v = *reinterpret_cast<const float2*>(Q + (size_t)row * D_DIM + col);
            __half hx = __float2half_rn(v.x), hy = __float2half_rn(v.y);
            __half lx = __float2half_rn(v.x - __half2float(hx));
            __half ly = __float2half_rn(v.y - __half2float(hy));
            qh[t][p] = packh2(hx, hy);
            ql[t][p] = packh2(lx, ly);
        }
    }

    // ---- mask generation, phase-staggered across SM slot-mates ----
    uint32_t kb_cur = 0;
    if (upfront) {
        // even slot: all 32 words now (ALU burst overlaps mate's tensor body)
        for (int kt = 0; kt < 32; ++kt)
            smask[kt * 128 + tid] = tile_mask_word(gbase + (unsigned)(kt * 64));
    } else {
        // odd slot: only tile 0 now; rest computed one iteration ahead
        kb_cur = tile_mask_word(gbase);
    }

    float oacc[16][4];
    #pragma unroll
    for (int i = 0; i < 16; ++i)
        #pragma unroll
        for (int j = 0; j < 4; ++j) oacc[i][j] = 0.0f;
    float m0 = -CUDART_INF_F, m1 = -CUDART_INF_F;
    float l0 = 0.0f, l1 = 0.0f;

    const int lr  = lane & 7;
    const int seg = lane >> 3;
    const uint32_t k_lane_off = (uint32_t)(lr * 272 + ((seg & 1) * 8 + (seg >> 1) * 16) * 2);
    const uint32_t v_lane_off = (uint32_t)(((seg & 1) * 8 + lr) * 272 + ((seg >> 1) * 8) * 2);
    const uint32_t kh_base0 = smem_u32 + k_lane_off;
    const uint32_t kl_base0 = smem_u32 + (uint32_t)TILE_B + k_lane_off;
    const uint32_t vh_base  = smem_u32 + (uint32_t)OFF_V + v_lane_off;

    for (int kt = 0; kt < 32; ++kt) {
        const uint32_t cur = (uint32_t)(kt & 1) * KBUF_B;

        __syncthreads();

        stage_v(smem_u32 + OFF_V, bh, kt * BN, tid);
        cp_commit();
        if (kt + 1 < 32)
            stage_k(smem_u32 + ((kt & 1) ? OFF_K0 : OFF_K1), bh, (kt + 1) * BN, tid);
        cp_commit();

        cp_wait<2>();
        __syncthreads();

        uint32_t keepbits = upfront ? smask[kt * 128 + tid] : kb_cur;

        // lazy mode: compute NEXT tile's word here — fully independent of this
        // iteration's math, interleaves into the MMA region's issue slack.
        uint32_t kb_next = 0;
        if (!upfront && kt + 1 < 32)
            kb_next = tile_mask_word(gbase + (unsigned)((kt + 1) * 64));

        const uint32_t kh_base = kh_base0 + cur;
        const uint32_t kl_base = kl_base0 + cur;

        // ---- S = Q @ K^T (qh*kh + ql*kh + qh*kl) ----
        float sacc[8][4];
        #pragma unroll
        for (int n = 0; n < 8; ++n) {
            sacc[n][0] = 0.0f; sacc[n][1] = 0.0f;
            sacc[n][2] = 0.0f; sacc[n][3] = 0.0f;
            const uint32_t rowoff = (uint32_t)(n * 8 * 272);
            #pragma unroll
            for (int dp = 0; dp < 4; ++dp) {
                uint32_t bh0, bh1, bh2, bh3, bl0, bl1, bl2, bl3;
                ldsm_x4(bh0, bh1, bh2, bh3, kh_base + rowoff + (uint32_t)(dp * 64));
                ldsm_x4(bl0, bl1, bl2, bl3, kl_base + rowoff + (uint32_t)(dp * 64));
                mma_f16(sacc[n], qh[2 * dp],     bh0, bh1);
                mma_f16(sacc[n], qh[2 * dp + 1], bh2, bh3);
                mma_f16(sacc[n], ql[2 * dp],     bh0, bh1);
                mma_f16(sacc[n], ql[2 * dp + 1], bh2, bh3);
                mma_f16(sacc[n], qh[2 * dp],     bl0, bl1);
                mma_f16(sacc[n], qh[2 * dp + 1], bl2, bl3);
            }
        }

        // ---- online softmax (exp2 domain) ----
        float mx0 = -CUDART_INF_F, mx1 = -CUDART_INF_F;
        #pragma unroll
        for (int n = 0; n < 8; ++n) {
            sacc[n][0] *= scl; sacc[n][1] *= scl;
            sacc[n][2] *= scl; sacc[n][3] *= scl;
            mx0 = fmaxf(mx0, fmaxf(sacc[n][0], sacc[n][1]));
            mx1 = fmaxf(mx1, fmaxf(sacc[n][2], sacc[n][3]));
        }
        mx0 = fmaxf(mx0, __shfl_xor_sync(0xffffffffu, mx0, 1));
        mx0 = fmaxf(mx0, __shfl_xor_sync(0xffffffffu, mx0, 2));
        mx1 = fmaxf(mx1, __shfl_xor_sync(0xffffffffu, mx1, 1));
        mx1 = fmaxf(mx1, __shfl_xor_sync(0xffffffffu, mx1, 2));
        float mn0 = fmaxf(m0, mx0), mn1 = fmaxf(m1, mx1);
        float sc0 = exp2f(m0 - mn0), sc1 = exp2f(m1 - mn1);
        m0 = mn0; m1 = mn1;
        float rs0 = 0.0f, rs1 = 0.0f;
        #pragma unroll
        for (int n = 0; n < 8; ++n) {
            sacc[n][0] = exp2f(sacc[n][0] - mn0);
            sacc[n][1] = exp2f(sacc[n][1] - mn0);
            sacc[n][2] = exp2f(sacc[n][2] - mn1);
            sacc[n][3] = exp2f(sacc[n][3] - mn1);
            rs0 += sacc[n][0] + sacc[n][1];
            rs1 += sacc[n][2] + sacc[n][3];
        }
        rs0 += __shfl_xor_sync(0xffffffffu, rs0, 1);
        rs0 += __shfl_xor_sync(0xffffffffu, rs0, 2);
        rs1 += __shfl_xor_sync(0xffffffffu, rs1, 1);
        rs1 += __shfl_xor_sync(0xffffffffu, rs1, 2);
        l0 = l0 * sc0 + rs0;
        l1 = l1 * sc1 + rs1;
        #pragma unroll
        for (int i = 0; i < 16; ++i) {
            oacc[i][0] *= sc0; oacc[i][1] *= sc0;
            oacc[i][2] *= sc1; oacc[i][3] *= sc1;
        }

        // ---- apply mask bits + pack P ----
        uint32_t pfr[8][2];
        #pragma unroll
        for (int n = 0; n < 8; ++n) {
            float p00 = ((keepbits >> (4 * n + 0)) & 1u) ? sacc[n][0] : 0.0f;
            float p01 = ((keepbits >> (4 * n + 1)) & 1u) ? sacc[n][1] : 0.0f;
            float p10 = ((keepbits >> (4 * n + 2)) & 1u) ? sacc[n][2] : 0.0f;
            float p11 = ((keepbits >> (4 * n + 3)) & 1u) ? sacc[n][3] : 0.0f;
            pfr[n][0] = packh2(__float2half_rn(p00), __float2half_rn(p01));
            pfr[n][1] = packh2(__float2half_rn(p10), __float2half_rn(p11));
        }

        cp_wait<1>();
        __syncthreads();

        // ---- O += P @ V ----
        #pragma unroll
        for (int kk = 0; kk < 4; ++kk) {
            uint32_t a[4] = { pfr[2 * kk][0], pfr[2 * kk][1],
                              pfr[2 * kk + 1][0], pfr[2 * kk + 1][1] };
            const uint32_t kkoff = (uint32_t)(kk * 16 * 272);
            #pragma unroll
            for (int np = 0; np < 8; ++np) {
                uint32_t b0, b1, b2, b3;
                ldsm_x4_t(b0, b1, b2, b3, vh_base + kkoff + (uint32_t)(np * 32));
                mma_f16(oacc[2 * np],     a, b0, b1);
                mma_f16(oacc[2 * np + 1], a, b2, b3);
            }
        }

        kb_cur = kb_next;
    }

    // ---- epilogue: out = 2*o/l + residual(x2) ----
    const float il0 = 2.0f / l0;
    const float il1 = 2.0f / l1;
    #pragma unroll
    for (int np = 0; np < 16; ++np) {
        int col = 8 * np + 2 * c;
        const float2 r0 = *reinterpret_cast<const float2*>(R + (size_t)qrow * D_DIM + col);
        const float2 r1 = *reinterpret_cast<const float2*>(R + (size_t)(qrow + 8) * D_DIM + col);
        float2 w0, w1;
        w0.x = fmaf(oacc[np][0], il0, r0.x);
        w0.y = fmaf(oacc[np][1], il0, r0.y);
        w1.x = fmaf(oacc[np][2], il1, r1.x);
        w1.y = fmaf(oacc[np][3], il1, r1.y);
        *reinterpret_cast<float2*>(O + (size_t)qrow * D_DIM + col) = w0;
        *reinterpret_cast<float2*>(O + (size_t)(qrow + 8) * D_DIM + col) = w1;
    }
}

extern "C" void kernel_launch(void* const* d_in, const int* in_sizes, int n_in,
                              void* d_out, int out_size) {
    const float* x1 = (const float*)d_in[0];
    const float* x2 = (const float*)d_in[1];
    const float* x3 = (const float*)d_in[2];
    float* out = (float*)d_out;
    (void)in_sizes; (void)n_in; (void)out_size;

    cudaFuncSetAttribute(attn_mma_kernel,
                         cudaFuncAttributeMaxDynamicSharedMemorySize, SMEM_BYTES);

    convert_kernel<<<1024, 256>>>(x1, x2);
    dim3 grid(S_LEN / BM, 32);    // (32 q-tiles, 32 bh)
    attn_mma_kernel<<<grid, NT, SMEM_BYTES>>>(x1, x2, x3, out);
}

// round 13
// speedup vs baseline: 1.4446x; 1.4446x over previous
#include <cuda_runtime.h>
#include <cuda_fp16.h>
#include <math_constants.h>
#include <cstdint>

// Round 13: R8 pipeline with 2-pass S-GEMM (K-lo correction dropped).
//  - s = (qh + ql) @ kh^T : exact-q times fp16(K). Error = q*kl ~ 2e-3 abs on
//    scores -> ~3-6e-4 output rel (gate 1e-3). Kl eliminated everywhere:
//    convert writes 1/3 less, K staging halves, S-MMAs 192->128/tile/warp,
//    S-ldsm 64->32, smem 87KB->52KB.
//  - mask kernel: R8 fragment layout + R11-validated trimmed threefry
//    (bit-identical keep bits).
//  - attn otherwise identical to R8 (best passing, 718.5us).

#define S_LEN 2048
#define D_DIM 128
#define BM 64
#define BN 64
#define NT 128
#define NELEM (2 * 16 * S_LEN * D_DIM)
#define NMASKW (1 << 22)

#define TILE_B 17408                    // one 64x128 fp16 tile (64*272 B)
#define OFF_K0 0
#define OFF_K1 TILE_B                   // 17408
#define OFF_V  (2 * TILE_B)             // 34816
#define SMEM_BYTES (3 * TILE_B)         // 52224 -> 2 CTAs/SM easily

__device__ __half g_Kh[NELEM];
__device__ __half g_Vh[NELEM];
__device__ uint32_t g_mask[NMASKW];

// ---------------- prologue: fp32 -> fp16 (K hi only, V hi) ----------------
__global__ void __launch_bounds__(256, 4)
convert_kernel(const float* __restrict__ x1, const float* __restrict__ x2)
{
    int stride = gridDim.x * blockDim.x;
    for (int i = blockIdx.x * blockDim.x + threadIdx.x; i < NELEM / 4; i += stride) {
        float4 k = reinterpret_cast<const float4*>(x2)[i];
        float4 v = reinterpret_cast<const float4*>(x1)[i];
        reinterpret_cast<__half2*>(g_Kh)[2*i] =
            __halves2half2(__float2half_rn(k.x), __float2half_rn(k.y));
        reinterpret_cast<__half2*>(g_Kh)[2*i+1] =
            __halves2half2(__float2half_rn(k.z), __float2half_rn(k.w));
        reinterpret_cast<__half2*>(g_Vh)[2*i] =
            __halves2half2(__float2half_rn(v.x), __float2half_rn(v.y));
        reinterpret_cast<__half2*>(g_Vh)[2*i+1] =
            __halves2half2(__float2half_rn(v.z), __float2half_rn(v.w));
    }
}

// ---------------- threefry (JAX partitionable, key=(0,42)), trimmed ----------------
// Returns y with MSB==1 iff KEEP. Bit-identical to validated R8 bits (R11/R12
// measured the same rel_err to the last digit).
__device__ __forceinline__ unsigned tf_rotl(unsigned x, int r) {
    return __funnelshift_l(x, x, r);
}
__device__ __forceinline__ unsigned threefry_keep_msb(unsigned g) {
    const unsigned ks1 = 42u;
    const unsigned ks2 = 0x1BD11BDAu ^ 42u;
    unsigned x0 = 0u;
    unsigned x1 = g + ks1;
#define TF_R(r)            { x0 += x1; x1 = tf_rotl(x1, (r)) ^ x0; }
#define TF_IR(ka, kb, r)   { x1 += (kb); x0 = x0 + (ka) + x1; x1 = tf_rotl(x1, (r)) ^ x0; }
    TF_R(13) TF_R(15) TF_R(26) TF_R(6)
    TF_IR(ks1, ks2 + 1u, 17) TF_R(29) TF_R(16) TF_R(24)
    TF_IR(ks2, 2u,       13) TF_R(15) TF_R(26) TF_R(6)
    TF_IR(0u,  ks1 + 3u, 17) TF_R(29) TF_R(16) TF_R(24)
    TF_IR(ks1, ks2 + 4u, 13) TF_R(15) TF_R(26) TF_R(6)
#undef TF_R
#undef TF_IR
    return ~((x0 + ks2) ^ (x1 + 5u));   // XNOR: single LOP3
}

// ---------------- mask kernel (BM=64 fragment layout, as in R8) ----------------
// word idx = ((((bh*32 + qtile)*4 + warp)*32 + kt)*32 + lane
__global__ void __launch_bounds__(256)
mask_kernel()
{
    unsigned idx = blockIdx.x * 256u + threadIdx.x;
    unsigned lane  = idx & 31u;
    unsigned kt    = (idx >> 5) & 31u;
    unsigned warp  = (idx >> 10) & 3u;
    unsigned qtile = (idx >> 12) & 31u;
    unsigned bh    = idx >> 17;
    unsigned g = lane >> 2, c = lane & 3u;
    unsigned qrow = qtile * 64u + warp * 16u + g;
    unsigned gt = (bh * 2048u + qrow) * 2048u + 2u * c + kt * 64u;

    uint32_t keepbits = 0u;
    #pragma unroll
    for (int n = 0; n < 8; ++n) {
        unsigned gi = gt + (unsigned)(8 * n);
        unsigned y0 = threefry_keep_msb(gi);
        unsigned y1 = threefry_keep_msb(gi + 1u);
        unsigned y2 = threefry_keep_msb(gi + 16384u);
        unsigned y3 = threefry_keep_msb(gi + 16385u);
        keepbits = (keepbits >> 1) | (y0 & 0x80000000u);
        keepbits = (keepbits >> 1) | (y1 & 0x80000000u);
        keepbits = (keepbits >> 1) | (y2 & 0x80000000u);
        keepbits = (keepbits >> 1) | (y3 & 0x80000000u);
    }
    g_mask[idx] = keepbits;
}

__device__ __forceinline__ uint32_t packh2(__half a, __half b) {
    __half2 h = __halves2half2(a, b);
    return *reinterpret_cast<uint32_t*>(&h);
}
__device__ __forceinline__ void mma_f16(float c[4], const uint32_t a[4],
                                        uint32_t b0, uint32_t b1) {
    asm volatile(
        "mma.sync.aligned.m16n8k16.row.col.f32.f16.f16.f32 "
        "{%0,%1,%2,%3}, {%4,%5,%6,%7}, {%8,%9}, {%0,%1,%2,%3};\n"
        : "+f"(c[0]), "+f"(c[1]), "+f"(c[2]), "+f"(c[3])
        : "r"(a[0]), "r"(a[1]), "r"(a[2]), "r"(a[3]), "r"(b0), "r"(b1));
}
__device__ __forceinline__ void ldsm_x4(uint32_t& r0, uint32_t& r1,
                                        uint32_t& r2, uint32_t& r3, uint32_t addr) {
    asm volatile("ldmatrix.sync.aligned.m8n8.x4.shared.b16 {%0,%1,%2,%3}, [%4];"
                 : "=r"(r0), "=r"(r1), "=r"(r2), "=r"(r3) : "r"(addr));
}
__device__ __forceinline__ void ldsm_x4_t(uint32_t& r0, uint32_t& r1,
                                          uint32_t& r2, uint32_t& r3, uint32_t addr) {
    asm volatile("ldmatrix.sync.aligned.m8n8.x4.trans.shared.b16 {%0,%1,%2,%3}, [%4];"
                 : "=r"(r0), "=r"(r1), "=r"(r2), "=r"(r3) : "r"(addr));
}
__device__ __forceinline__ void cp_async16(uint32_t dst, const void* src) {
    asm volatile("cp.async.cg.shared.global [%0], [%1], 16;" :: "r"(dst), "l"(src));
}
__device__ __forceinline__ void cp_commit() { asm volatile("cp.async.commit_group;"); }
template <int N> __device__ __forceinline__ void cp_wait() {
    asm volatile("cp.async.wait_group %0;" :: "n"(N));
}

// stage Kh tile (1024 16B chunks)
__device__ __forceinline__ void stage_k(uint32_t buf_b, int bh, int k0, int tid)
{
    const size_t kbase = (size_t)bh * (S_LEN * D_DIM) + (size_t)k0 * D_DIM;
    #pragma unroll
    for (int it = 0; it < 8; ++it) {
        int id  = tid + it * NT;        // 0..1023
        int row = id >> 4;
        int col = id & 15;
        cp_async16(buf_b + (uint32_t)(row * 272 + col * 16),
                   g_Kh + kbase + (size_t)row * D_DIM + col * 8);
    }
}
__device__ __forceinline__ void stage_v(uint32_t vbuf_b, int bh, int k0, int tid)
{
    const size_t kbase = (size_t)bh * (S_LEN * D_DIM) + (size_t)k0 * D_DIM;
    #pragma unroll
    for (int it = 0; it < 8; ++it) {
        int id  = tid + it * NT;
        int row = id >> 4;
        int col = id & 15;
        cp_async16(vbuf_b + (uint32_t)(row * 272 + col * 16),
                   g_Vh + kbase + (size_t)row * D_DIM + col * 8);
    }
}

__global__ void __launch_bounds__(NT, 2)
attn_mma_kernel(const float* __restrict__ x1,
                const float* __restrict__ x2,
                const float* __restrict__ x3,
                float* __restrict__ out)
{
    extern __shared__ __half smh[];

    const int tid  = threadIdx.x;
    const int warp = tid >> 5;
    const int lane = tid & 31;
    const int g    = lane >> 2;
    const int c    = lane & 3;
    const int bh   = blockIdx.y;
    const int q0   = blockIdx.x * BM;
    const int qrow = q0 + warp * 16 + g;

    const float* Q = x1 + (size_t)bh * (S_LEN * D_DIM);
    const float* R = x2 + (size_t)bh * (S_LEN * D_DIM);
    float* O = out + (size_t)bh * (S_LEN * D_DIM);
    const float scl = (1.0f / x3[bh]) * 1.4426950408889634f;

    const uint32_t* mrow = g_mask
        + ((((size_t)bh * 32 + blockIdx.x) * 4 + warp) * 32) * 32 + lane;

    const uint32_t smem_u32 = (uint32_t)__cvta_generic_to_shared(smh);

    stage_k(smem_u32 + OFF_K0, bh, 0, tid);
    cp_commit();

    // ---- Q fragments resident (hi + lo split; exact q = qh + ql) ----
    uint32_t qh[8][4], ql[8][4];
    #pragma unroll
    for (int t = 0; t < 8; ++t) {
        #pragma unroll
        for (int p = 0; p < 4; ++p) {
            int row = qrow + (p & 1) * 8;
            int col = 16 * t + (p >> 1) * 8 + 2 * c;
            float2 v = *reinterpret_cast<const float2*>(Q + (size_t)row * D_DIM + col);
            __half hx = __float2half_rn(v.x), hy = __float2half_rn(v.y);
            __half lx = __float2half_rn(v.x - __half2float(hx));
            __half ly = __float2half_rn(v.y - __half2float(hy));
            qh[t][p] = packh2(hx, hy);
            ql[t][p] = packh2(lx, ly);
        }
    }

    float oacc[16][4];
    #pragma unroll
    for (int i = 0; i < 16; ++i)
        #pragma unroll
        for (int j = 0; j < 4; ++j) oacc[i][j] = 0.0f;
    float m0 = -CUDART_INF_F, m1 = -CUDART_INF_F;
    float l0 = 0.0f, l1 = 0.0f;

    const int lr  = lane & 7;
    const int seg = lane >> 3;
    const uint32_t k_lane_off = (uint32_t)(lr * 272 + ((seg & 1) * 8 + (seg >> 1) * 16) * 2);
    const uint32_t v_lane_off = (uint32_t)(((seg & 1) * 8 + lr) * 272 + ((seg >> 1) * 8) * 2);
    const uint32_t kh_base0 = smem_u32 + k_lane_off;
    const uint32_t vh_base  = smem_u32 + (uint32_t)OFF_V + v_lane_off;

    for (int kt = 0; kt < 32; ++kt) {
        const uint32_t cur = (uint32_t)(kt & 1) * (uint32_t)TILE_B;
        uint32_t keepbits = mrow[kt * 32];

        __syncthreads();

        stage_v(smem_u32 + OFF_V, bh, kt * BN, tid);
        cp_commit();
        if (kt + 1 < 32)
            stage_k(smem_u32 + ((kt & 1) ? OFF_K0 : OFF_K1), bh, (kt + 1) * BN, tid);
        cp_commit();

        cp_wait<2>();     // K(kt) resident
        __syncthreads();

        const uint32_t kh_base = kh_base0 + cur;

        // ---- S = (qh + ql) @ Kh^T : 2 passes, 4 MMAs per (n, dp) ----
        float sacc[8][4];
        #pragma unroll
        for (int n = 0; n < 8; ++n) {
            sacc[n][0] = 0.0f; sacc[n][1] = 0.0f;
            sacc[n][2] = 0.0f; sacc[n][3] = 0.0f;
            const uint32_t rowoff = (uint32_t)(n * 8 * 272);
            #pragma unroll
            for (int dp = 0; dp < 4; ++dp) {
                uint32_t bh0, bh1, bh2, bh3;
                ldsm_x4(bh0, bh1, bh2, bh3, kh_base + rowoff + (uint32_t)(dp * 64));
                mma_f16(sacc[n], qh[2 * dp],     bh0, bh1);
                mma_f16(sacc[n], qh[2 * dp + 1], bh2, bh3);
                mma_f16(sacc[n], ql[2 * dp],     bh0, bh1);
                mma_f16(sacc[n], ql[2 * dp + 1], bh2, bh3);
            }
        }

        // ---- online softmax (exp2 domain) ----
        float mx0 = -CUDART_INF_F, mx1 = -CUDART_INF_F;
        #pragma unroll
        for (int n = 0; n < 8; ++n) {
            sacc[n][0] *= scl; sacc[n][1] *= scl;
            sacc[n][2] *= scl; sacc[n][3] *= scl;
            mx0 = fmaxf(mx0, fmaxf(sacc[n][0], sacc[n][1]));
            mx1 = fmaxf(mx1, fmaxf(sacc[n][2], sacc[n][3]));
        }
        mx0 = fmaxf(mx0, __shfl_xor_sync(0xffffffffu, mx0, 1));
        mx0 = fmaxf(mx0, __shfl_xor_sync(0xffffffffu, mx0, 2));
        mx1 = fmaxf(mx1, __shfl_xor_sync(0xffffffffu, mx1, 1));
        mx1 = fmaxf(mx1, __shfl_xor_sync(0xffffffffu, mx1, 2));
        float mn0 = fmaxf(m0, mx0), mn1 = fmaxf(m1, mx1);
        float sc0 = exp2f(m0 - mn0), sc1 = exp2f(m1 - mn1);
        m0 = mn0; m1 = mn1;
        float rs0 = 0.0f, rs1 = 0.0f;
        #pragma unroll
        for (int n = 0; n < 8; ++n) {
            sacc[n][0] = exp2f(sacc[n][0] - mn0);
            sacc[n][1] = exp2f(sacc[n][1] - mn0);
            sacc[n][2] = exp2f(sacc[n][2] - mn1);
            sacc[n][3] = exp2f(sacc[n][3] - mn1);
            rs0 += sacc[n][0] + sacc[n][1];
            rs1 += sacc[n][2] + sacc[n][3];
        }
        rs0 += __shfl_xor_sync(0xffffffffu, rs0, 1);
        rs0 += __shfl_xor_sync(0xffffffffu, rs0, 2);
        rs1 += __shfl_xor_sync(0xffffffffu, rs1, 1);
        rs1 += __shfl_xor_sync(0xffffffffu, rs1, 2);
        l0 = l0 * sc0 + rs0;
        l1 = l1 * sc1 + rs1;
        #pragma unroll
        for (int i = 0; i < 16; ++i) {
            oacc[i][0] *= sc0; oacc[i][1] *= sc0;
            oacc[i][2] *= sc1; oacc[i][3] *= sc1;
        }

        // ---- apply mask bits + pack P ----
        uint32_t pfr[8][2];
        #pragma unroll
        for (int n = 0; n < 8; ++n) {
            float p00 = ((keepbits >> (4 * n + 0)) & 1u) ? sacc[n][0] : 0.0f;
            float p01 = ((keepbits >> (4 * n + 1)) & 1u) ? sacc[n][1] : 0.0f;
            float p10 = ((keepbits >> (4 * n + 2)) & 1u) ? sacc[n][2] : 0.0f;
            float p11 = ((keepbits >> (4 * n + 3)) & 1u) ? sacc[n][3] : 0.0f;
            pfr[n][0] = packh2(__float2half_rn(p00), __float2half_rn(p01));
            pfr[n][1] = packh2(__float2half_rn(p10), __float2half_rn(p11));
        }

        cp_wait<1>();     // V(kt) resident
        __syncthreads();

        // ---- O += P @ V ----
        #pragma unroll
        for (int kk = 0; kk < 4; ++kk) {
            uint32_t a[4] = { pfr[2 * kk][0], pfr[2 * kk][1],
                              pfr[2 * kk + 1][0], pfr[2 * kk + 1][1] };
            const uint32_t kkoff = (uint32_t)(kk * 16 * 272);
            #pragma unroll
            for (int np = 0; np < 8; ++np) {
                uint32_t b0, b1, b2, b3;
                ldsm_x4_t(b0, b1, b2, b3, vh_base + kkoff + (uint32_t)(np * 32));
                mma_f16(oacc[2 * np],     a, b0, b1);
                mma_f16(oacc[2 * np + 1], a, b2, b3);
            }
        }
    }

    // ---- epilogue: out = 2*o/l + residual(x2) ----
    const float il0 = 2.0f / l0;
    const float il1 = 2.0f / l1;
    #pragma unroll
    for (int np = 0; np < 16; ++np) {
        int col = 8 * np + 2 * c;
        const float2 r0 = *reinterpret_cast<const float2*>(R + (size_t)qrow * D_DIM + col);
        const float2 r1 = *reinterpret_cast<const float2*>(R + (size_t)(qrow + 8) * D_DIM + col);
        float2 w0, w1;
        w0.x = fmaf(oacc[np][0], il0, r0.x);
        w0.y = fmaf(oacc[np][1], il0, r0.y);
        w1.x = fmaf(oacc[np][2], il1, r1.x);
        w1.y = fmaf(oacc[np][3], il1, r1.y);
        *reinterpret_cast<float2*>(O + (size_t)qrow * D_DIM + col) = w0;
        *reinterpret_cast<float2*>(O + (size_t)(qrow + 8) * D_DIM + col) = w1;
    }
}

extern "C" void kernel_launch(void* const* d_in, const int* in_sizes, int n_in,
                              void* d_out, int out_size) {
    const float* x1 = (const float*)d_in[0];
    const float* x2 = (const float*)d_in[1];
    const float* x3 = (const float*)d_in[2];
    float* out = (float*)d_out;
    (void)in_sizes; (void)n_in; (void)out_size;

    cudaFuncSetAttribute(attn_mma_kernel,
                         cudaFuncAttributeMaxDynamicSharedMemorySize, SMEM_BYTES);

    convert_kernel<<<1024, 256>>>(x1, x2);
    mask_kernel<<<NMASKW / 256, 256>>>();
    dim3 grid(S_LEN / BM, 32);
    attn_mma_kernel<<<grid, NT, SMEM_BYTES>>>(x1, x2, x3, out);
}

// round 14
// speedup vs baseline: 1.5814x; 1.0946x over previous
#include <cuda_runtime.h>
#include <cuda_fp16.h>
#include <math_constants.h>
#include <cstdint>

// Round 14: 1-pass S-GEMM (both lo-correction passes dropped).
//  - s = qh @ kh^T : fp16(Q) x fp16(K), fp32 accum. Measured error ledger:
//    base (PV fp16) 1.54e-4, k-lo-drop +5.2e-4 (quadrature, R13-measured);
//    q-lo-drop is symmetric -> predicted rel_err sqrt(5.42^2+5.2^2) ~ 7.5e-4.
//  - S-MMAs 128->64 per tile/warp (total stream -33%), ql regs freed.
//  - mask kernel unchanged (ALU-pipe floor, bit-exact threefry).
//  - attn otherwise identical to R13 (624.1us best).

#define S_LEN 2048
#define D_DIM 128
#define BM 64
#define BN 64
#define NT 128
#define NELEM (2 * 16 * S_LEN * D_DIM)
#define NMASKW (1 << 22)

#define TILE_B 17408                    // one 64x128 fp16 tile (64*272 B)
#define OFF_K0 0
#define OFF_K1 TILE_B                   // 17408
#define OFF_V  (2 * TILE_B)             // 34816
#define SMEM_BYTES (3 * TILE_B)         // 52224 -> 2 CTAs/SM

__device__ __half g_Kh[NELEM];
__device__ __half g_Vh[NELEM];
__device__ uint32_t g_mask[NMASKW];

// ---------------- prologue: fp32 -> fp16 (K hi, V hi) ----------------
__global__ void __launch_bounds__(256, 4)
convert_kernel(const float* __restrict__ x1, const float* __restrict__ x2)
{
    int stride = gridDim.x * blockDim.x;
    for (int i = blockIdx.x * blockDim.x + threadIdx.x; i < NELEM / 4; i += stride) {
        float4 k = reinterpret_cast<const float4*>(x2)[i];
        float4 v = reinterpret_cast<const float4*>(x1)[i];
        reinterpret_cast<__half2*>(g_Kh)[2*i] =
            __halves2half2(__float2half_rn(k.x), __float2half_rn(k.y));
        reinterpret_cast<__half2*>(g_Kh)[2*i+1] =
            __halves2half2(__float2half_rn(k.z), __float2half_rn(k.w));
        reinterpret_cast<__half2*>(g_Vh)[2*i] =
            __halves2half2(__float2half_rn(v.x), __float2half_rn(v.y));
        reinterpret_cast<__half2*>(g_Vh)[2*i+1] =
            __halves2half2(__float2half_rn(v.z), __float2half_rn(v.w));
    }
}

// ---------------- threefry (JAX partitionable, key=(0,42)), trimmed ----------------
__device__ __forceinline__ unsigned tf_rotl(unsigned x, int r) {
    return __funnelshift_l(x, x, r);
}
__device__ __forceinline__ unsigned threefry_keep_msb(unsigned g) {
    const unsigned ks1 = 42u;
    const unsigned ks2 = 0x1BD11BDAu ^ 42u;
    unsigned x0 = 0u;
    unsigned x1 = g + ks1;
#define TF_R(r)            { x0 += x1; x1 = tf_rotl(x1, (r)) ^ x0; }
#define TF_IR(ka, kb, r)   { x1 += (kb); x0 = x0 + (ka) + x1; x1 = tf_rotl(x1, (r)) ^ x0; }
    TF_R(13) TF_R(15) TF_R(26) TF_R(6)
    TF_IR(ks1, ks2 + 1u, 17) TF_R(29) TF_R(16) TF_R(24)
    TF_IR(ks2, 2u,       13) TF_R(15) TF_R(26) TF_R(6)
    TF_IR(0u,  ks1 + 3u, 17) TF_R(29) TF_R(16) TF_R(24)
    TF_IR(ks1, ks2 + 4u, 13) TF_R(15) TF_R(26) TF_R(6)
#undef TF_R
#undef TF_IR
    return ~((x0 + ks2) ^ (x1 + 5u));   // XNOR: MSB==1 iff KEEP
}

// ---------------- mask kernel (BM=64 fragment layout) ----------------
__global__ void __launch_bounds__(256)
mask_kernel()
{
    unsigned idx = blockIdx.x * 256u + threadIdx.x;
    unsigned lane  = idx & 31u;
    unsigned kt    = (idx >> 5) & 31u;
    unsigned warp  = (idx >> 10) & 3u;
    unsigned qtile = (idx >> 12) & 31u;
    unsigned bh    = idx >> 17;
    unsigned g = lane >> 2, c = lane & 3u;
    unsigned qrow = qtile * 64u + warp * 16u + g;
    unsigned gt = (bh * 2048u + qrow) * 2048u + 2u * c + kt * 64u;

    uint32_t keepbits = 0u;
    #pragma unroll
    for (int n = 0; n < 8; ++n) {
        unsigned gi = gt + (unsigned)(8 * n);
        unsigned y0 = threefry_keep_msb(gi);
        unsigned y1 = threefry_keep_msb(gi + 1u);
        unsigned y2 = threefry_keep_msb(gi + 16384u);
        unsigned y3 = threefry_keep_msb(gi + 16385u);
        keepbits = (keepbits >> 1) | (y0 & 0x80000000u);
        keepbits = (keepbits >> 1) | (y1 & 0x80000000u);
        keepbits = (keepbits >> 1) | (y2 & 0x80000000u);
        keepbits = (keepbits >> 1) | (y3 & 0x80000000u);
    }
    g_mask[idx] = keepbits;
}

__device__ __forceinline__ uint32_t packh2(__half a, __half b) {
    __half2 h = __halves2half2(a, b);
    return *reinterpret_cast<uint32_t*>(&h);
}
__device__ __forceinline__ void mma_f16(float c[4], const uint32_t a[4],
                                        uint32_t b0, uint32_t b1) {
    asm volatile(
        "mma.sync.aligned.m16n8k16.row.col.f32.f16.f16.f32 "
        "{%0,%1,%2,%3}, {%4,%5,%6,%7}, {%8,%9}, {%0,%1,%2,%3};\n"
        : "+f"(c[0]), "+f"(c[1]), "+f"(c[2]), "+f"(c[3])
        : "r"(a[0]), "r"(a[1]), "r"(a[2]), "r"(a[3]), "r"(b0), "r"(b1));
}
__device__ __forceinline__ void ldsm_x4(uint32_t& r0, uint32_t& r1,
                                        uint32_t& r2, uint32_t& r3, uint32_t addr) {
    asm volatile("ldmatrix.sync.aligned.m8n8.x4.shared.b16 {%0,%1,%2,%3}, [%4];"
                 : "=r"(r0), "=r"(r1), "=r"(r2), "=r"(r3) : "r"(addr));
}
__device__ __forceinline__ void ldsm_x4_t(uint32_t& r0, uint32_t& r1,
                                          uint32_t& r2, uint32_t& r3, uint32_t addr) {
    asm volatile("ldmatrix.sync.aligned.m8n8.x4.trans.shared.b16 {%0,%1,%2,%3}, [%4];"
                 : "=r"(r0), "=r"(r1), "=r"(r2), "=r"(r3) : "r"(addr));
}
__device__ __forceinline__ void cp_async16(uint32_t dst, const void* src) {
    asm volatile("cp.async.cg.shared.global [%0], [%1], 16;" :: "r"(dst), "l"(src));
}
__device__ __forceinline__ void cp_commit() { asm volatile("cp.async.commit_group;"); }
template <int N> __device__ __forceinline__ void cp_wait() {
    asm volatile("cp.async.wait_group %0;" :: "n"(N));
}

__device__ __forceinline__ void stage_k(uint32_t buf_b, int bh, int k0, int tid)
{
    const size_t kbase = (size_t)bh * (S_LEN * D_DIM) + (size_t)k0 * D_DIM;
    #pragma unroll
    for (int it = 0; it < 8; ++it) {
        int id  = tid + it * NT;        // 0..1023
        int row = id >> 4;
        int col = id & 15;
        cp_async16(buf_b + (uint32_t)(row * 272 + col * 16),
                   g_Kh + kbase + (size_t)row * D_DIM + col * 8);
    }
}
__device__ __forceinline__ void stage_v(uint32_t vbuf_b, int bh, int k0, int tid)
{
    const size_t kbase = (size_t)bh * (S_LEN * D_DIM) + (size_t)k0 * D_DIM;
    #pragma unroll
    for (int it = 0; it < 8; ++it) {
        int id  = tid + it * NT;
        int row = id >> 4;
        int col = id & 15;
        cp_async16(vbuf_b + (uint32_t)(row * 272 + col * 16),
                   g_Vh + kbase + (size_t)row * D_DIM + col * 8);
    }
}

__global__ void __launch_bounds__(NT, 2)
attn_mma_kernel(const float* __restrict__ x1,
                const float* __restrict__ x2,
                const float* __restrict__ x3,
                float* __restrict__ out)
{
    extern __shared__ __half smh[];

    const int tid  = threadIdx.x;
    const int warp = tid >> 5;
    const int lane = tid & 31;
    const int g    = lane >> 2;
    const int c    = lane & 3;
    const int bh   = blockIdx.y;
    const int q0   = blockIdx.x * BM;
    const int qrow = q0 + warp * 16 + g;

    const float* Q = x1 + (size_t)bh * (S_LEN * D_DIM);
    const float* R = x2 + (size_t)bh * (S_LEN * D_DIM);
    float* O = out + (size_t)bh * (S_LEN * D_DIM);
    const float scl = (1.0f / x3[bh]) * 1.4426950408889634f;

    const uint32_t* mrow = g_mask
        + ((((size_t)bh * 32 + blockIdx.x) * 4 + warp) * 32) * 32 + lane;

    const uint32_t smem_u32 = (uint32_t)__cvta_generic_to_shared(smh);

    stage_k(smem_u32 + OFF_K0, bh, 0, tid);
    cp_commit();

    // ---- Q fragments resident (fp16 hi only) ----
    uint32_t qh[8][4];
    #pragma unroll
    for (int t = 0; t < 8; ++t) {
        #pragma unroll
        for (int p = 0; p < 4; ++p) {
            int row = qrow + (p & 1) * 8;
            int col = 16 * t + (p >> 1) * 8 + 2 * c;
            float2 v = *reinterpret_cast<const float2*>(Q + (size_t)row * D_DIM + col);
            qh[t][p] = packh2(__float2half_rn(v.x), __float2half_rn(v.y));
        }
    }

    float oacc[16][4];
    #pragma unroll
    for (int i = 0; i < 16; ++i)
        #pragma unroll
        for (int j = 0; j < 4; ++j) oacc[i][j] = 0.0f;
    float m0 = -CUDART_INF_F, m1 = -CUDART_INF_F;
    float l0 = 0.0f, l1 = 0.0f;

    const int lr  = lane & 7;
    const int seg = lane >> 3;
    const uint32_t k_lane_off = (uint32_t)(lr * 272 + ((seg & 1) * 8 + (seg >> 1) * 16) * 2);
    const uint32_t v_lane_off = (uint32_t)(((seg & 1) * 8 + lr) * 272 + ((seg >> 1) * 8) * 2);
    const uint32_t kh_base0 = smem_u32 + k_lane_off;
    const uint32_t vh_base  = smem_u32 + (uint32_t)OFF_V + v_lane_off;

    for (int kt = 0; kt < 32; ++kt) {
        const uint32_t cur = (uint32_t)(kt & 1) * (uint32_t)TILE_B;
        uint32_t keepbits = mrow[kt * 32];

        __syncthreads();

        stage_v(smem_u32 + OFF_V, bh, kt * BN, tid);
        cp_commit();
        if (kt + 1 < 32)
            stage_k(smem_u32 + ((kt & 1) ? OFF_K0 : OFF_K1), bh, (kt + 1) * BN, tid);
        cp_commit();

        cp_wait<2>();     // K(kt) resident
        __syncthreads();

        const uint32_t kh_base = kh_base0 + cur;

        // ---- S = qh @ Kh^T : 1 pass, 2 MMAs per (n, dp) ----
        float sacc[8][4];
        #pragma unroll
        for (int n = 0; n < 8; ++n) {
            sacc[n][0] = 0.0f; sacc[n][1] = 0.0f;
            sacc[n][2] = 0.0f; sacc[n][3] = 0.0f;
            const uint32_t rowoff = (uint32_t)(n * 8 * 272);
            #pragma unroll
            for (int dp = 0; dp < 4; ++dp) {
                uint32_t bh0, bh1, bh2, bh3;
                ldsm_x4(bh0, bh1, bh2, bh3, kh_base + rowoff + (uint32_t)(dp * 64));
                mma_f16(sacc[n], qh[2 * dp],     bh0, bh1);
                mma_f16(sacc[n], qh[2 * dp + 1], bh2, bh3);
            }
        }

        // ---- online softmax (exp2 domain) ----
        float mx0 = -CUDART_INF_F, mx1 = -CUDART_INF_F;
        #pragma unroll
        for (int n = 0; n < 8; ++n) {
            sacc[n][0] *= scl; sacc[n][1] *= scl;
            sacc[n][2] *= scl; sacc[n][3] *= scl;
            mx0 = fmaxf(mx0, fmaxf(sacc[n][0], sacc[n][1]));
            mx1 = fmaxf(mx1, fmaxf(sacc[n][2], sacc[n][3]));
        }
        mx0 = fmaxf(mx0, __shfl_xor_sync(0xffffffffu, mx0, 1));
        mx0 = fmaxf(mx0, __shfl_xor_sync(0xffffffffu, mx0, 2));
        mx1 = fmaxf(mx1, __shfl_xor_sync(0xffffffffu, mx1, 1));
        mx1 = fmaxf(mx1, __shfl_xor_sync(0xffffffffu, mx1, 2));
        float mn0 = fmaxf(m0, mx0), mn1 = fmaxf(m1, mx1);
        float sc0 = exp2f(m0 - mn0), sc1 = exp2f(m1 - mn1);
        m0 = mn0; m1 = mn1;
        float rs0 = 0.0f, rs1 = 0.0f;
        #pragma unroll
        for (int n = 0; n < 8; ++n) {
            sacc[n][0] = exp2f(sacc[n][0] - mn0);
            sacc[n][1] = exp2f(sacc[n][1] - mn0);
            sacc[n][2] = exp2f(sacc[n][2] - mn1);
            sacc[n][3] = exp2f(sacc[n][3] - mn1);
            rs0 += sacc[n][0] + sacc[n][1];
            rs1 += sacc[n][2] + sacc[n][3];
        }
        rs0 += __shfl_xor_sync(0xffffffffu, rs0, 1);
        rs0 += __shfl_xor_sync(0xffffffffu, rs0, 2);
        rs1 += __shfl_xor_sync(0xffffffffu, rs1, 1);
        rs1 += __shfl_xor_sync(0xffffffffu, rs1, 2);
        l0 = l0 * sc0 + rs0;
        l1 = l1 * sc1 + rs1;
        #pragma unroll
        for (int i = 0; i < 16; ++i) {
            oacc[i][0] *= sc0; oacc[i][1] *= sc0;
            oacc[i][2] *= sc1; oacc[i][3] *= sc1;
        }

        // ---- apply mask bits + pack P ----
        uint32_t pfr[8][2];
        #pragma unroll
        for (int n = 0; n < 8; ++n) {
            float p00 = ((keepbits >> (4 * n + 0)) & 1u) ? sacc[n][0] : 0.0f;
            float p01 = ((keepbits >> (4 * n + 1)) & 1u) ? sacc[n][1] : 0.0f;
            float p10 = ((keepbits >> (4 * n + 2)) & 1u) ? sacc[n][2] : 0.0f;
            float p11 = ((keepbits >> (4 * n + 3)) & 1u) ? sacc[n][3] : 0.0f;
            pfr[n][0] = packh2(__float2half_rn(p00), __float2half_rn(p01));
            pfr[n][1] = packh2(__float2half_rn(p10), __float2half_rn(p11));
        }

        cp_wait<1>();     // V(kt) resident
        __syncthreads();

        // ---- O += P @ V ----
        #pragma unroll
        for (int kk = 0; kk < 4; ++kk) {
            uint32_t a[4] = { pfr[2 * kk][0], pfr[2 * kk][1],
                              pfr[2 * kk + 1][0], pfr[2 * kk + 1][1] };
            const uint32_t kkoff = (uint32_t)(kk * 16 * 272);
            #pragma unroll
            for (int np = 0; np < 8; ++np) {
                uint32_t b0, b1, b2, b3;
                ldsm_x4_t(b0, b1, b2, b3, vh_base + kkoff + (uint32_t)(np * 32));
                mma_f16(oacc[2 * np],     a, b0, b1);
                mma_f16(oacc[2 * np + 1], a, b2, b3);
            }
        }
    }

    // ---- epilogue: out = 2*o/l + residual(x2) ----
    const float il0 = 2.0f / l0;
    const float il1 = 2.0f / l1;
    #pragma unroll
    for (int np = 0; np < 16; ++np) {
        int col = 8 * np + 2 * c;
        const float2 r0 = *reinterpret_cast<const float2*>(R + (size_t)qrow * D_DIM + col);
        const float2 r1 = *reinterpret_cast<const float2*>(R + (size_t)(qrow + 8) * D_DIM + col);
        float2 w0, w1;
        w0.x = fmaf(oacc[np][0], il0, r0.x);
        w0.y = fmaf(oacc[np][1], il0, r0.y);
        w1.x = fmaf(oacc[np][2], il1, r1.x);
        w1.y = fmaf(oacc[np][3], il1, r1.y);
        *reinterpret_cast<float2*>(O + (size_t)qrow * D_DIM + col) = w0;
        *reinterpret_cast<float2*>(O + (size_t)(qrow + 8) * D_DIM + col) = w1;
    }
}

extern "C" void kernel_launch(void* const* d_in, const int* in_sizes, int n_in,
                              void* d_out, int out_size) {
    const float* x1 = (const float*)d_in[0];
    const float* x2 = (const float*)d_in[1];
    const float* x3 = (const float*)d_in[2];
    float* out = (float*)d_out;
    (void)in_sizes; (void)n_in; (void)out_size;

    cudaFuncSetAttribute(attn_mma_kernel,
                         cudaFuncAttributeMaxDynamicSharedMemorySize, SMEM_BYTES);

    convert_kernel<<<1024, 256>>>(x1, x2);
    mask_kernel<<<NMASKW / 256, 256>>>();
    dim3 grid(S_LEN / BM, 32);
    attn_mma_kernel<<<grid, NT, SMEM_BYTES>>>(x1, x2, x3, out);
}